// round 1
// baseline (speedup 1.0000x reference)
#include <cuda_runtime.h>
#include <cuda_bf16.h>

#define Bsz   256
#define Tsz   512
#define Csz   128
#define Lsz   64
#define Ssz   129
#define SP    132          // padded lattice stride
#define BLANKC 127
#define NEGV  (-1e30f)

// scratch: lp_z[b][t][s] = log_softmax(y_pred[b,t])[z[s]]
__device__ float g_lpz[(size_t)Bsz * Tsz * SP];

// ---------------------------------------------------------------------------
// Kernel 1: per-(b,t) log-softmax + gather into extended-label lattice.
// grid = (T, B), block = 128 (one thread per class; thread s also emits state s,
// thread 0 additionally emits state 128 = trailing blank).
// ---------------------------------------------------------------------------
__global__ __launch_bounds__(128)
void ctc_softmax_gather(const float* __restrict__ y_pred,
                        const int*   __restrict__ y_true) {
    const int t   = blockIdx.x;
    const int b   = blockIdx.y;
    const int tid = threadIdx.x;
    const int lane = tid & 31, wid = tid >> 5;

    __shared__ float shx[Csz];
    __shared__ float red[8];   // [0..3] max, [4..7] sum

    const float* rowp = y_pred + ((size_t)b * Tsz + t) * Csz;
    float x = rowp[tid];
    shx[tid] = x;

    // row max
    float m = x;
    #pragma unroll
    for (int o = 16; o; o >>= 1) m = fmaxf(m, __shfl_xor_sync(0xffffffffu, m, o));
    if (lane == 0) red[wid] = m;
    __syncthreads();
    const float M = fmaxf(fmaxf(red[0], red[1]), fmaxf(red[2], red[3]));

    // row sum of exp
    float e = __expf(x - M);
    #pragma unroll
    for (int o = 16; o; o >>= 1) e += __shfl_xor_sync(0xffffffffu, e, o);
    if (lane == 0) red[4 + wid] = e;
    __syncthreads();
    const float lse = M + __logf(red[4] + red[5] + red[6] + red[7]);

    // emit lattice state s = tid (and s = 128 from tid 0)
    const int s = tid;
    const int z = (s & 1) ? y_true[b * Lsz + (s >> 1)] : BLANKC;
    float* outrow = g_lpz + ((size_t)b * Tsz + t) * SP;
    outrow[s] = shx[z] - lse;
    if (tid == 0) outrow[128] = shx[BLANKC] - lse;
}

// ---------------------------------------------------------------------------
// Kernel 2: serial alpha recurrence over t. One block per batch row.
// 128 threads: thread s owns state s; thread 127 also owns state 128.
// Double-buffered alpha in shared -> exactly ONE barrier per time step.
// ---------------------------------------------------------------------------
__global__ __launch_bounds__(128)
void ctc_alpha(const int* __restrict__ y_true,
               const int* __restrict__ input_length,
               const int* __restrict__ label_length,
               float*     __restrict__ out) {
    const int b = blockIdx.x;
    const int s = threadIdx.x;       // 0..127

    __shared__ float alpha[2][SP];

    const float* row = g_lpz + (size_t)b * Tsz * SP;

    // skip transition allowed only for odd s >= 3 with differing labels
    bool skip = false;
    if ((s & 1) && s >= 3) {
        const int l  = y_true[b * Lsz + (s >> 1)];
        const int l2 = y_true[b * Lsz + (s >> 1) - 1];
        skip = (l != l2);
    }
    const int T_run = input_length[b];

    // t = 0 init
    const float lp0 = row[s];
    alpha[0][s] = (s <= 1) ? lp0 : NEGV;
    if (s == 127) alpha[0][128] = NEGV;
    __syncthreads();

    int cur = 0;
    // prefetch t = 1
    float lpn  = row[SP + s];
    float lpn2 = 0.f;
    if (s == 127) lpn2 = row[SP + 128];

    for (int t = 1; t < Tsz; ++t) {
        const float lp  = lpn;
        const float lp2 = lpn2;
        if (t + 1 < Tsz) {
            lpn = row[(size_t)(t + 1) * SP + s];
            if (s == 127) lpn2 = row[(size_t)(t + 1) * SP + 128];
        }

        const float a0 = alpha[cur][s];
        const float a1 = (s >= 1) ? alpha[cur][s - 1] : NEGV;
        const float a2 = skip ? alpha[cur][s - 2] : NEGV;

        float m   = fmaxf(a0, fmaxf(a1, a2));
        float val = m + __logf(__expf(a0 - m) + __expf(a1 - m) + __expf(a2 - m));
        alpha[cur ^ 1][s] = (t < T_run) ? (val + lp) : a0;

        if (s == 127) {   // state 128 (trailing blank): only self + s-1 paths
            const float b0 = alpha[cur][128];
            const float b1 = alpha[cur][127];
            const float mm = fmaxf(b0, b1);
            const float v2 = mm + __logf(__expf(b0 - mm) + __expf(b1 - mm));
            alpha[cur ^ 1][128] = (t < T_run) ? (v2 + lp2) : b0;
        }

        cur ^= 1;
        __syncthreads();   // orders writes(t) before reads(t+1); reads precede arrival
    }

    if (s == 0) {
        const int   ll  = label_length[b];
        const float aE  = alpha[cur][2 * ll];
        const float aE2 = alpha[cur][2 * ll - 1];
        const float m   = fmaxf(aE, aE2);
        out[b] = -(m + __logf(__expf(aE - m) + __expf(aE2 - m)));
    }
}

// ---------------------------------------------------------------------------
extern "C" void kernel_launch(void* const* d_in, const int* in_sizes, int n_in,
                              void* d_out, int out_size) {
    // map inputs by size (dict order: y_true, y_pred, input_length, label_length)
    const int*   y_true = nullptr;
    const float* y_pred = nullptr;
    const int*   ilen   = nullptr;
    const int*   llen   = nullptr;
    for (int i = 0; i < n_in; ++i) {
        const int sz = in_sizes[i];
        if (sz == Bsz * Tsz * Csz)      y_pred = (const float*)d_in[i];
        else if (sz == Bsz * Lsz)       y_true = (const int*)d_in[i];
        else if (sz == Bsz) {
            if (!ilen) ilen = (const int*)d_in[i];
            else       llen = (const int*)d_in[i];
        }
    }
    float* out = (float*)d_out;

    dim3 g1(Tsz, Bsz);
    ctc_softmax_gather<<<g1, 128>>>(y_pred, y_true);
    ctc_alpha<<<Bsz, 128>>>(y_true, ilen, llen, out);
}

// round 2
// speedup vs baseline: 2.9907x; 2.9907x over previous
#include <cuda_runtime.h>
#include <cuda_bf16.h>

#define Bsz   256
#define Tsz   512
#define Csz   128
#define Lsz   64
#define BLANKC 127
#define NEGV  (-1e30f)
#define PF    8            // prefetch ring depth

// lse[b][t] = logsumexp over classes of y_pred[b,t,:]
__device__ float g_lse[(size_t)Bsz * Tsz];

// ---------------------------------------------------------------------------
// Kernel 1: log-sum-exp per (b,t) row. One warp per row, float4 loads.
// grid = B*T/4 blocks of 128 threads.
// ---------------------------------------------------------------------------
__global__ __launch_bounds__(128)
void ctc_lse(const float* __restrict__ y_pred) {
    const int row  = blockIdx.x * 4 + (threadIdx.x >> 5);
    const int lane = threadIdx.x & 31;

    const float4 v = reinterpret_cast<const float4*>(y_pred + (size_t)row * Csz)[lane];
    float m = fmaxf(fmaxf(v.x, v.y), fmaxf(v.z, v.w));
    #pragma unroll
    for (int o = 16; o; o >>= 1) m = fmaxf(m, __shfl_xor_sync(0xffffffffu, m, o));

    float e = __expf(v.x - m) + __expf(v.y - m) + __expf(v.z - m) + __expf(v.w - m);
    #pragma unroll
    for (int o = 16; o; o >>= 1) e += __shfl_xor_sync(0xffffffffu, e, o);

    if (lane == 0) g_lse[row] = m + __logf(e);
}

// ---------------------------------------------------------------------------
// Kernel 2: serial alpha recurrence. One block per batch row, 160 threads
// (5 warps): thread s owns lattice state s for s = 0..128; s>128 idle-but-
// syncing. Depth-PF register ring prefetch hides DRAM latency (MLP=8).
// Gathers y_pred[b,t,z_s] directly (no lp_z intermediate).
// ---------------------------------------------------------------------------
__global__ __launch_bounds__(160)
void ctc_alpha(const float* __restrict__ y_pred,
               const int*   __restrict__ y_true,
               const int*   __restrict__ input_length,
               const int*   __restrict__ label_length,
               float*       __restrict__ out) {
    const int b = blockIdx.x;
    const int s = threadIdx.x;              // 0..159
    const int sc = (s <= 128) ? s : 128;    // clamp for safe loads

    __shared__ float alpha[2][136];

    // class index for this lattice state
    const int z = (sc & 1) ? y_true[b * Lsz + (sc >> 1)] : BLANKC;

    // skip transition: odd s >= 3 and label differs from label two states back
    bool skip = false;
    if ((sc & 1) && sc >= 3) {
        skip = (z != y_true[b * Lsz + (sc >> 1) - 1]);
    }
    const int T_run = input_length[b];

    const float* xptr = y_pred + (size_t)b * Tsz * Csz + z;   // stride Csz per t
    const float* lptr = g_lse + b * Tsz;

    // t = 0 init
    {
        const float lp0 = xptr[0] - lptr[0];
        if (s <= 128) alpha[0][s] = (s <= 1) ? lp0 : NEGV;
    }

    // fill prefetch rings for t = 1..PF
    float xr[PF], lr[PF];
    #pragma unroll
    for (int i = 0; i < PF; ++i) {
        const int tt = (1 + i < Tsz) ? (1 + i) : (Tsz - 1);
        xr[i] = xptr[(size_t)tt * Csz];
        lr[i] = lptr[tt];
    }
    __syncthreads();

    int cur = 0;
    for (int t = 1; t < Tsz; t += PF) {
        #pragma unroll
        for (int j = 0; j < PF; ++j) {
            const int tc = t + j;
            if (tc >= Tsz) break;

            const float lp = xr[j] - lr[j];
            // issue prefetch for tc + PF (clamped; tail loads redundant, unused)
            {
                const int tp = (tc + PF < Tsz) ? (tc + PF) : (Tsz - 1);
                xr[j] = xptr[(size_t)tp * Csz];
                lr[j] = lptr[tp];
            }

            if (s <= 128) {
                const float a0 = alpha[cur][s];
                const float a1 = (s >= 1) ? alpha[cur][s - 1] : NEGV;
                const float a2 = skip ? alpha[cur][s - 2] : NEGV;

                const float m   = fmaxf(a0, fmaxf(a1, a2));
                const float val = m + __logf(__expf(a0 - m) + __expf(a1 - m) +
                                             __expf(a2 - m));
                alpha[cur ^ 1][s] = (tc < T_run) ? (val + lp) : a0;
            }
            cur ^= 1;
            __syncthreads();   // writes(t) before reads(t+1); reads precede arrival
        }
    }

    if (s == 0) {
        const int   ll  = label_length[b];
        const float aE  = alpha[cur][2 * ll];
        const float aE2 = alpha[cur][2 * ll - 1];
        const float m   = fmaxf(aE, aE2);
        out[b] = -(m + __logf(__expf(aE - m) + __expf(aE2 - m)));
    }
}

// ---------------------------------------------------------------------------
extern "C" void kernel_launch(void* const* d_in, const int* in_sizes, int n_in,
                              void* d_out, int out_size) {
    const int*   y_true = nullptr;
    const float* y_pred = nullptr;
    const int*   ilen   = nullptr;
    const int*   llen   = nullptr;
    for (int i = 0; i < n_in; ++i) {
        const int sz = in_sizes[i];
        if (sz == Bsz * Tsz * Csz)      y_pred = (const float*)d_in[i];
        else if (sz == Bsz * Lsz)       y_true = (const int*)d_in[i];
        else if (sz == Bsz) {
            if (!ilen) ilen = (const int*)d_in[i];
            else       llen = (const int*)d_in[i];
        }
    }
    float* out = (float*)d_out;

    ctc_lse<<<(Bsz * Tsz) / 4, 128>>>(y_pred);
    ctc_alpha<<<Bsz, 160>>>(y_pred, y_true, ilen, llen, out);
}